// round 9
// baseline (speedup 1.0000x reference)
#include <cuda_runtime.h>
#include <cuda_fp16.h>
#include <stdint.h>

// NeuralODE RK4, fp16 mma (m16n8k16, fp32 accum), sm_103a.
// R9: 32 CTAs x 256 threads; each CTA integrates TWO independent 16-row
// streams, interleaved at GEMM granularity so one stream's epilogue/barrier
// glue hides under the other's mainloop. Fragment-major activation buffers,
// paired-kt W1 in SMEM, W2 persistent in registers, biases in SMEM,
// tanh.approx epilogue. 2 barriers per feval-PAIR (was 2 per feval).

#define ZDIM 256
#define TLEN 128
#define NCTA 32
#define WREC (16 * 32 * 32)       // uint2 records per matrix in WfG

#define OFF_W1  0                 // paired-kt W1 fragments: 128 KB
#define OFF_A0  131072            // stream-0 A fragments: 8 KB
#define OFF_A1  139264
#define OFF_H0  147456
#define OFF_H1  155648
#define OFF_B1  163840            // b1: 256 floats
#define OFF_B2  164864
#define SMEM_TOT 165888

__device__ uint2 WfG[2 * WREC];   // fragment-layout fp16 weights (prep output)

// ---- prep: W[k][n] row-major fp32 -> fp16 B-fragment layout ----
__global__ void prep_kernel(const float* __restrict__ W1, const float* __restrict__ W2)
{
    int idx = blockIdx.x * blockDim.x + threadIdx.x;
    if (idx >= 2 * WREC) return;
    int lane = idx & 31;
    int nt   = (idx >> 5) & 31;
    int kt   = (idx >> 10) & 15;
    int g    = idx >> 14;
    const float* W = g ? W2 : W1;
    int k0 = kt * 16 + 2 * (lane & 3);
    int n  = nt * 8 + (lane >> 2);
    __half2 lo = __floats2half2_rn(W[k0 * ZDIM + n],       W[(k0 + 1) * ZDIM + n]);
    __half2 hi = __floats2half2_rn(W[(k0 + 8) * ZDIM + n], W[(k0 + 9) * ZDIM + n]);
    uint2 v;
    v.x = *reinterpret_cast<unsigned*>(&lo);
    v.y = *reinterpret_cast<unsigned*>(&hi);
    WfG[idx] = v;
}

#define MMA16(ACC, A0, A1, A2, A3, BX, BY) \
    asm volatile("mma.sync.aligned.m16n8k16.row.col.f32.f16.f16.f32 " \
                 "{%0,%1,%2,%3}, {%4,%5,%6,%7}, {%8,%9}, {%0,%1,%2,%3};" \
                 : "+f"(ACC[0]), "+f"(ACC[1]), "+f"(ACC[2]), "+f"(ACC[3]) \
                 : "r"(A0), "r"(A1), "r"(A2), "r"(A3), "r"(BX), "r"(BY))

__device__ __forceinline__ float fast_tanh(float x) {
    float y; asm("tanh.approx.f32 %0, %1;" : "=f"(y) : "f"(x)); return y;
}
__device__ __forceinline__ unsigned pack2(float a, float b) {
    __half2 h = __floats2half2_rn(a, b);
    return *reinterpret_cast<unsigned*>(&h);
}

// GEMM1: A quads fragment-major SMEM, B (W1) paired-kt LDS.128. acc init 0.
__device__ __forceinline__ void gemm_w1(const uint4* __restrict__ AfU4,
                                        const uint4* __restrict__ w1p,
                                        int lane, int nt0, int aidx,
                                        float acc[4][4])
{
#pragma unroll
    for (int t = 0; t < 4; t++)
#pragma unroll
        for (int d = 0; d < 4; d++) acc[t][d] = 0.0f;

    uint4 bw[4];
#pragma unroll
    for (int t = 0; t < 4; t++) bw[t] = w1p[(nt0 + t) * 32 + lane];

#pragma unroll
    for (int kt2 = 0; kt2 < 8; kt2++) {
        uint4 av0 = AfU4[kt2 * 64 + aidx];
        uint4 av1 = AfU4[kt2 * 64 + 32 + aidx];
        uint4 bn[4];
        if (kt2 < 7) {
#pragma unroll
            for (int t = 0; t < 4; t++)
                bn[t] = w1p[((kt2 + 1) * 32 + nt0 + t) * 32 + lane];
        }
#pragma unroll
        for (int t = 0; t < 4; t++)
            MMA16(acc[t], av0.x, av0.y, av0.z, av0.w, bw[t].x, bw[t].y);
#pragma unroll
        for (int t = 0; t < 4; t++)
            MMA16(acc[t], av1.x, av1.y, av1.z, av1.w, bw[t].z, bw[t].w);
        if (kt2 < 7) {
#pragma unroll
            for (int t = 0; t < 4; t++) bw[t] = bn[t];
        }
    }
}

// GEMM2: A quads fragment-major SMEM, B (W2) persistent registers. acc init 0.
__device__ __forceinline__ void gemm_w2(const uint4* __restrict__ HfU4,
                                        const uint2 w2r[16][4],
                                        int aidx, float acc[4][4])
{
#pragma unroll
    for (int t = 0; t < 4; t++)
#pragma unroll
        for (int d = 0; d < 4; d++) acc[t][d] = 0.0f;

#pragma unroll
    for (int kt2 = 0; kt2 < 8; kt2++) {
        uint4 av0 = HfU4[kt2 * 64 + aidx];
        uint4 av1 = HfU4[kt2 * 64 + 32 + aidx];
#pragma unroll
        for (int t = 0; t < 4; t++)
            MMA16(acc[t], av0.x, av0.y, av0.z, av0.w,
                  w2r[2 * kt2][t].x, w2r[2 * kt2][t].y);
#pragma unroll
        for (int t = 0; t < 4; t++)
            MMA16(acc[t], av1.x, av1.y, av1.z, av1.w,
                  w2r[2 * kt2 + 1][t].x, w2r[2 * kt2 + 1][t].y);
    }
}

__global__ void __launch_bounds__(256, 1)
node_kernel(const float* __restrict__ z0, const float* __restrict__ tg,
            const float* __restrict__ b1, const float* __restrict__ b2,
            float* __restrict__ out)
{
    extern __shared__ unsigned char smem_raw[];
    uint4* w1p  = reinterpret_cast<uint4*>(smem_raw + OFF_W1);
    uint4* Af0  = reinterpret_cast<uint4*>(smem_raw + OFF_A0);
    uint4* Af1  = reinterpret_cast<uint4*>(smem_raw + OFF_A1);
    uint4* Hf0  = reinterpret_cast<uint4*>(smem_raw + OFF_H0);
    uint4* Hf1  = reinterpret_cast<uint4*>(smem_raw + OFF_H1);
    float* b1s  = reinterpret_cast<float*>(smem_raw + OFF_B1);
    float* b2s  = reinterpret_cast<float*>(smem_raw + OFF_B2);

    const int tid  = threadIdx.x;
    const int lane = tid & 31;
    const int wid  = tid >> 5;           // 0..7
    const int nt0  = wid * 4;            // 4 n-tiles per warp
    const int r0   = lane >> 2;
    const int c0   = lane & 3;
    const int row0 = blockIdx.x * 32;    // 32 rows per CTA (2 streams x 16)
    const int aidx = r0 * 4 + c0;
    const int sidx0 = (2 * wid) * 32 + aidx;
    const int sidx1 = sidx0 + 32;

    // ---- W1 fragments -> paired-kt SMEM layout (once) ----
    for (int i = tid; i < 8192; i += 256) {
        int l   = i & 31;
        int nt  = (i >> 5) & 31;
        int kt2 = i >> 10;
        uint2 lo = WfG[((2 * kt2) * 32 + nt) * 32 + l];
        uint2 hi = WfG[((2 * kt2 + 1) * 32 + nt) * 32 + l];
        uint4 v; v.x = lo.x; v.y = lo.y; v.z = hi.x; v.w = hi.y;
        w1p[i] = v;
    }
    if (tid < ZDIM) { b1s[tid] = b1[tid]; b2s[tid] = b2[tid]; }

    // ---- W2 fragments -> persistent registers (once, 128 regs) ----
    uint2 w2r[16][4];
    {
        const uint2* w2g = WfG + WREC;
#pragma unroll
        for (int kt = 0; kt < 16; kt++)
#pragma unroll
            for (int t = 0; t < 4; t++)
                w2r[kt][t] = w2g[(kt * 32 + nt0 + t) * 32 + lane];
    }

    float za[4][4], aa[4][4];   // stream 0 state / RK4 accum
    float zb[4][4], ab[4][4];   // stream 1
    float acc[4][4];

#define STAGE_WRITE(BUF, V)                                                    \
    do {                                                                       \
        uint4 q0, q1;                                                          \
        q0.x = pack2(V[0][0], V[0][1]); q0.y = pack2(V[0][2], V[0][3]);        \
        q0.z = pack2(V[1][0], V[1][1]); q0.w = pack2(V[1][2], V[1][3]);        \
        q1.x = pack2(V[2][0], V[2][1]); q1.y = pack2(V[2][2], V[2][3]);        \
        q1.z = pack2(V[3][0], V[3][1]); q1.w = pack2(V[3][2], V[3][3]);        \
        (BUF)[sidx0] = q0;                                                     \
        (BUF)[sidx1] = q1;                                                     \
    } while (0)

    // ---- initial state (both streams) ----
#pragma unroll
    for (int t = 0; t < 4; t++) {
        int cb = (nt0 + t) * 8 + 2 * c0;
        float2 v0 = *reinterpret_cast<const float2*>(&z0[(row0 + r0) * ZDIM + cb]);
        float2 v1 = *reinterpret_cast<const float2*>(&z0[(row0 + r0 + 8) * ZDIM + cb]);
        za[t][0] = v0.x; za[t][1] = v0.y; za[t][2] = v1.x; za[t][3] = v1.y;
        float2 w0 = *reinterpret_cast<const float2*>(&z0[(row0 + 16 + r0) * ZDIM + cb]);
        float2 w1v = *reinterpret_cast<const float2*>(&z0[(row0 + 16 + r0 + 8) * ZDIM + cb]);
        zb[t][0] = w0.x; zb[t][1] = w0.y; zb[t][2] = w1v.x; zb[t][3] = w1v.y;
    }
    STAGE_WRITE(Af0, za);
    STAGE_WRITE(Af1, zb);
    __syncthreads();

    // Epilogue A: hv = tanh(acc + b1), write H buffer.
#define EPI_TANH(HBUF)                                                         \
    do {                                                                       \
        float hv[4][4];                                                        \
        _Pragma("unroll")                                                      \
        for (int t = 0; t < 4; t++) {                                          \
            float2 bp = *reinterpret_cast<const float2*>(                      \
                &b1s[(nt0 + t) * 8 + 2 * c0]);                                 \
            hv[t][0] = fast_tanh(acc[t][0] + bp.x);                            \
            hv[t][1] = fast_tanh(acc[t][1] + bp.y);                            \
            hv[t][2] = fast_tanh(acc[t][2] + bp.x);                            \
            hv[t][3] = fast_tanh(acc[t][3] + bp.y);                            \
        }                                                                      \
        STAGE_WRITE(HBUF, hv);                                                 \
    } while (0)

    // Epilogue B (RK4 stage): kf = acc + b2; update ZR/AR; stage st into ABUF.
#define EPI_RK4(ZR, AR, ABUF, STAGE_ID)                                        \
    do {                                                                       \
        float st[4][4];                                                        \
        _Pragma("unroll")                                                      \
        for (int t = 0; t < 4; t++) {                                          \
            float2 bp = *reinterpret_cast<const float2*>(                      \
                &b2s[(nt0 + t) * 8 + 2 * c0]);                                 \
            _Pragma("unroll")                                                  \
            for (int d = 0; d < 4; d++) {                                      \
                float kfv = acc[t][d] + ((d & 1) ? bp.y : bp.x);               \
                if (STAGE_ID == 0) {                                           \
                    AR[t][d] = fmaf(h6, kfv, ZR[t][d]);                        \
                    st[t][d] = fmaf(h2, kfv, ZR[t][d]);                        \
                } else if (STAGE_ID == 1) {                                    \
                    AR[t][d] = fmaf(h3, kfv, AR[t][d]);                        \
                    st[t][d] = fmaf(h2, kfv, ZR[t][d]);                        \
                } else if (STAGE_ID == 2) {                                    \
                    AR[t][d] = fmaf(h3, kfv, AR[t][d]);                        \
                    st[t][d] = fmaf(hs, kfv, ZR[t][d]);                        \
                } else {                                                       \
                    ZR[t][d] = fmaf(h6, kfv, AR[t][d]);                        \
                    st[t][d] = ZR[t][d];                                       \
                }                                                              \
            }                                                                  \
        }                                                                      \
        STAGE_WRITE(ABUF, st);                                                 \
    } while (0)

    for (int s = 0; s < TLEN - 1; s++) {
        const float hs = tg[s + 1] - tg[s];
        const float h6 = hs * (1.0f / 6.0f);
        const float h3 = hs * (1.0f / 3.0f);
        const float h2 = hs * 0.5f;

#pragma unroll
        for (int stage = 0; stage < 4; stage++) {
            // ---- Phase A: GEMM1 both streams ----
            gemm_w1(Af0, w1p, lane, nt0, aidx, acc);
            EPI_TANH(Hf0);
            gemm_w1(Af1, w1p, lane, nt0, aidx, acc);
            EPI_TANH(Hf1);
            __syncthreads();

            // ---- Phase B: GEMM2 + RK4 both streams ----
            gemm_w2(Hf0, w2r, aidx, acc);
            EPI_RK4(za, aa, Af0, stage);
            gemm_w2(Hf1, w2r, aidx, acc);
            EPI_RK4(zb, ab, Af1, stage);
            __syncthreads();
        }
    }

#pragma unroll
    for (int t = 0; t < 4; t++) {
        int cb = (nt0 + t) * 8 + 2 * c0;
        float2 v0 = {za[t][0], za[t][1]};
        float2 v1 = {za[t][2], za[t][3]};
        *reinterpret_cast<float2*>(&out[(row0 + r0) * ZDIM + cb])          = v0;
        *reinterpret_cast<float2*>(&out[(row0 + r0 + 8) * ZDIM + cb])      = v1;
        float2 w0 = {zb[t][0], zb[t][1]};
        float2 w1v = {zb[t][2], zb[t][3]};
        *reinterpret_cast<float2*>(&out[(row0 + 16 + r0) * ZDIM + cb])     = w0;
        *reinterpret_cast<float2*>(&out[(row0 + 16 + r0 + 8) * ZDIM + cb]) = w1v;
    }
}

extern "C" void kernel_launch(void* const* d_in, const int* in_sizes, int n_in,
                              void* d_out, int out_size)
{
    const float* z0 = (const float*)d_in[0];
    const float* t  = (const float*)d_in[1];
    const float* W1 = (const float*)d_in[2];
    const float* b1 = (const float*)d_in[3];
    const float* W2 = (const float*)d_in[4];
    const float* b2 = (const float*)d_in[5];
    float* out = (float*)d_out;

    cudaFuncSetAttribute(node_kernel,
                         cudaFuncAttributeMaxDynamicSharedMemorySize, SMEM_TOT);

    prep_kernel<<<(2 * WREC + 255) / 256, 256>>>(W1, W2);
    node_kernel<<<NCTA, 256, SMEM_TOT>>>(z0, t, b1, b2, out);
}

// round 10
// speedup vs baseline: 1.1786x; 1.1786x over previous
#include <cuda_runtime.h>
#include <cuda_fp16.h>
#include <stdint.h>

// NeuralODE RK4, fp16 mma (m16n8k16, fp32 accum), sm_103a.
// R10: 32 CTAs x 256 threads, M=32 rows/CTA (two m16 tiles) so every B
// fragment feeds 2x MMAs. W1 in SMEM (LDS + prefetch), W2 LDG-streamed with
// rotating depth-3 register window filled during the tanh epilogue, RK4
// accumulator in SMEM (frees regs), z-state + biases in registers.

#define ZDIM 256
#define TLEN 128
#define NCTA 32

#define OFF_W1  0                 // paired-kt W1 fragments: 8192 uint4 = 128 KB
#define OFF_A   131072            // A fragments: 1024 uint4 = 16 KB (2 m-slabs)
#define OFF_H   147456            // H fragments: 16 KB
#define OFF_AR  163840            // RK4 accumulator: 2048 float4 = 32 KB
#define SMEM_TOT 196608

__device__ uint4 WfP[16384];      // paired-kt fragment weights: [W1 | W2]

// ---- prep: W[k][n] fp32 -> paired-kt fp16 B-fragment uint4 layout ----
// WfP[g*8192 + kt2*1024 + nt*32 + lane] = {frag(kt=2kt2), frag(kt=2kt2+1)}
__global__ void prep_kernel(const float* __restrict__ W1, const float* __restrict__ W2)
{
    int idx = blockIdx.x * blockDim.x + threadIdx.x;
    if (idx >= 16384) return;
    int lane = idx & 31;
    int nt   = (idx >> 5) & 31;
    int kt2  = (idx >> 10) & 7;
    int g    = idx >> 13;
    const float* W = g ? W2 : W1;
    int ke = kt2 * 32 + 2 * (lane & 3);      // even kt: k0
    int ko = ke + 16;                        // odd kt: k0
    int n  = nt * 8 + (lane >> 2);
    __half2 h;
    uint4 v;
    h = __floats2half2_rn(W[ke * ZDIM + n],       W[(ke + 1) * ZDIM + n]);
    v.x = *reinterpret_cast<unsigned*>(&h);
    h = __floats2half2_rn(W[(ke + 8) * ZDIM + n], W[(ke + 9) * ZDIM + n]);
    v.y = *reinterpret_cast<unsigned*>(&h);
    h = __floats2half2_rn(W[ko * ZDIM + n],       W[(ko + 1) * ZDIM + n]);
    v.z = *reinterpret_cast<unsigned*>(&h);
    h = __floats2half2_rn(W[(ko + 8) * ZDIM + n], W[(ko + 9) * ZDIM + n]);
    v.w = *reinterpret_cast<unsigned*>(&h);
    WfP[idx] = v;
}

#define MMA16(ACC, AV, BX, BY) \
    asm volatile("mma.sync.aligned.m16n8k16.row.col.f32.f16.f16.f32 " \
                 "{%0,%1,%2,%3}, {%4,%5,%6,%7}, {%8,%9}, {%0,%1,%2,%3};" \
                 : "+f"(ACC[0]), "+f"(ACC[1]), "+f"(ACC[2]), "+f"(ACC[3]) \
                 : "r"(AV.x), "r"(AV.y), "r"(AV.z), "r"(AV.w), "r"(BX), "r"(BY))

__device__ __forceinline__ float fast_tanh(float x) {
    float y; asm("tanh.approx.f32 %0, %1;" : "=f"(y) : "f"(x)); return y;
}
__device__ __forceinline__ unsigned pack2(float a, float b) {
    __half2 h = __floats2half2_rn(a, b);
    return *reinterpret_cast<unsigned*>(&h);
}

// GEMM1: A from fragment-major SMEM (2 m-slabs), B (W1) from SMEM paired-kt.
__device__ __forceinline__ void gemm_w1(const uint4* __restrict__ Af,
                                        const uint4* __restrict__ w1p,
                                        uint4 bw[4],
                                        int lane, int nt0, int aidx,
                                        const float bias[4][2],
                                        float acc[2][4][4])
{
#pragma unroll
    for (int m = 0; m < 2; m++)
#pragma unroll
        for (int t = 0; t < 4; t++) {
            acc[m][t][0] = bias[t][0]; acc[m][t][1] = bias[t][1];
            acc[m][t][2] = bias[t][0]; acc[m][t][3] = bias[t][1];
        }
#pragma unroll
    for (int kt2 = 0; kt2 < 8; kt2++) {
        uint4 av00 = Af[kt2 * 64 + aidx];
        uint4 av01 = Af[kt2 * 64 + 32 + aidx];
        uint4 av10 = Af[512 + kt2 * 64 + aidx];
        uint4 av11 = Af[512 + kt2 * 64 + 32 + aidx];
        uint4 bn[4];
        if (kt2 < 7) {
#pragma unroll
            for (int t = 0; t < 4; t++)
                bn[t] = w1p[(kt2 + 1) * 1024 + (nt0 + t) * 32 + lane];
        }
#pragma unroll
        for (int t = 0; t < 4; t++) {
            MMA16(acc[0][t], av00, bw[t].x, bw[t].y);
            MMA16(acc[0][t], av01, bw[t].z, bw[t].w);
            MMA16(acc[1][t], av10, bw[t].x, bw[t].y);
            MMA16(acc[1][t], av11, bw[t].z, bw[t].w);
        }
        if (kt2 < 7) {
#pragma unroll
            for (int t = 0; t < 4; t++) bw[t] = bn[t];
        }
    }
}

// GEMM2: A from fragment-major SMEM, B (W2) via LDG rotating depth-3 window.
__device__ __forceinline__ void gemm_w2(const uint4* __restrict__ Hf,
                                        const uint4* __restrict__ W2g,
                                        uint4 (&win)[3][4],
                                        int lane, int nt0, int aidx,
                                        const float bias[4][2],
                                        float acc[2][4][4])
{
#pragma unroll
    for (int m = 0; m < 2; m++)
#pragma unroll
        for (int t = 0; t < 4; t++) {
            acc[m][t][0] = bias[t][0]; acc[m][t][1] = bias[t][1];
            acc[m][t][2] = bias[t][0]; acc[m][t][3] = bias[t][1];
        }
#pragma unroll
    for (int kt2 = 0; kt2 < 8; kt2++) {
        uint4 cur[4];
#pragma unroll
        for (int t = 0; t < 4; t++) cur[t] = win[kt2 % 3][t];
        if (kt2 < 5) {
#pragma unroll
            for (int t = 0; t < 4; t++)
                win[kt2 % 3][t] =
                    __ldg(&W2g[(kt2 + 3) * 1024 + (nt0 + t) * 32 + lane]);
        }
        uint4 av00 = Hf[kt2 * 64 + aidx];
        uint4 av01 = Hf[kt2 * 64 + 32 + aidx];
        uint4 av10 = Hf[512 + kt2 * 64 + aidx];
        uint4 av11 = Hf[512 + kt2 * 64 + 32 + aidx];
#pragma unroll
        for (int t = 0; t < 4; t++) {
            MMA16(acc[0][t], av00, cur[t].x, cur[t].y);
            MMA16(acc[0][t], av01, cur[t].z, cur[t].w);
            MMA16(acc[1][t], av10, cur[t].x, cur[t].y);
            MMA16(acc[1][t], av11, cur[t].z, cur[t].w);
        }
    }
}

__global__ void __launch_bounds__(256, 1)
node_kernel(const float* __restrict__ z0, const float* __restrict__ tg,
            const float* __restrict__ b1, const float* __restrict__ b2,
            float* __restrict__ out)
{
    extern __shared__ unsigned char smem_raw[];
    uint4*  w1p  = reinterpret_cast<uint4*>(smem_raw + OFF_W1);
    uint4*  Af   = reinterpret_cast<uint4*>(smem_raw + OFF_A);
    uint4*  Hf   = reinterpret_cast<uint4*>(smem_raw + OFF_H);
    float4* ars4 = reinterpret_cast<float4*>(smem_raw + OFF_AR);

    const int tid  = threadIdx.x;
    const int lane = tid & 31;
    const int wid  = tid >> 5;           // 0..7
    const int nt0  = wid * 4;
    const int r0   = lane >> 2;
    const int c0   = lane & 3;
    const int row0 = blockIdx.x * 32;    // 32 rows per CTA
    const int aidx = r0 * 4 + c0;
    const int sidx0 = wid * 64 + aidx;   // kt-slab 2*wid
    const int sidx1 = sidx0 + 32;        // kt-slab 2*wid+1
    const uint4* W2g = WfP + 8192;

    // ---- W1 paired fragments -> SMEM (once) ----
    for (int i = tid; i < 8192; i += 256) w1p[i] = WfP[i];

    float bias1[4][2], bias2[4][2];
#pragma unroll
    for (int t = 0; t < 4; t++) {
        int cb = (nt0 + t) * 8 + 2 * c0;
        bias1[t][0] = b1[cb]; bias1[t][1] = b1[cb + 1];
        bias2[t][0] = b2[cb]; bias2[t][1] = b2[cb + 1];
    }

    float zr[2][4][4], acc[2][4][4];
    uint4 bw[4], win[3][4];

#define PRELOAD_BW() \
    do { _Pragma("unroll") \
         for (int t = 0; t < 4; t++) bw[t] = w1p[(nt0 + t) * 32 + lane]; } while (0)
#define PRELOAD_WIN() \
    do { _Pragma("unroll") \
         for (int ss = 0; ss < 3; ss++) \
             _Pragma("unroll") \
             for (int t = 0; t < 4; t++) \
                 win[ss][t] = __ldg(&W2g[ss * 1024 + (nt0 + t) * 32 + lane]); } while (0)

    // V is [2][4][4]; writes 2 uint4 per m-slab.
#define STAGE_WRITE(BUF, V)                                                    \
    do {                                                                       \
        _Pragma("unroll")                                                      \
        for (int m = 0; m < 2; m++) {                                          \
            uint4 q0, q1;                                                      \
            q0.x = pack2(V[m][0][0], V[m][0][1]);                              \
            q0.y = pack2(V[m][0][2], V[m][0][3]);                              \
            q0.z = pack2(V[m][1][0], V[m][1][1]);                              \
            q0.w = pack2(V[m][1][2], V[m][1][3]);                              \
            q1.x = pack2(V[m][2][0], V[m][2][1]);                              \
            q1.y = pack2(V[m][2][2], V[m][2][3]);                              \
            q1.z = pack2(V[m][3][0], V[m][3][1]);                              \
            q1.w = pack2(V[m][3][2], V[m][3][3]);                              \
            (BUF)[m * 512 + sidx0] = q0;                                       \
            (BUF)[m * 512 + sidx1] = q1;                                       \
        }                                                                      \
    } while (0)

    // ---- initial state ----
#pragma unroll
    for (int m = 0; m < 2; m++)
#pragma unroll
        for (int t = 0; t < 4; t++) {
            int cb = (nt0 + t) * 8 + 2 * c0;
            int rbase = row0 + m * 16;
            float2 v0 = *reinterpret_cast<const float2*>(&z0[(rbase + r0) * ZDIM + cb]);
            float2 v1 = *reinterpret_cast<const float2*>(&z0[(rbase + r0 + 8) * ZDIM + cb]);
            zr[m][t][0] = v0.x; zr[m][t][1] = v0.y;
            zr[m][t][2] = v1.x; zr[m][t][3] = v1.y;
        }
    STAGE_WRITE(Af, zr);
    PRELOAD_BW();
    __syncthreads();

#define EPI_TANH()                                                             \
    do {                                                                       \
        _Pragma("unroll")                                                      \
        for (int m = 0; m < 2; m++) {                                          \
            uint4 q0, q1;                                                      \
            q0.x = pack2(fast_tanh(acc[m][0][0]), fast_tanh(acc[m][0][1]));    \
            q0.y = pack2(fast_tanh(acc[m][0][2]), fast_tanh(acc[m][0][3]));    \
            q0.z = pack2(fast_tanh(acc[m][1][0]), fast_tanh(acc[m][1][1]));    \
            q0.w = pack2(fast_tanh(acc[m][1][2]), fast_tanh(acc[m][1][3]));    \
            q1.x = pack2(fast_tanh(acc[m][2][0]), fast_tanh(acc[m][2][1]));    \
            q1.y = pack2(fast_tanh(acc[m][2][2]), fast_tanh(acc[m][2][3]));    \
            q1.z = pack2(fast_tanh(acc[m][3][0]), fast_tanh(acc[m][3][1]));    \
            q1.w = pack2(fast_tanh(acc[m][3][2]), fast_tanh(acc[m][3][3]));    \
            Hf[m * 512 + sidx0] = q0;                                          \
            Hf[m * 512 + sidx1] = q1;                                          \
        }                                                                      \
    } while (0)

    // RK4 epilogue, stage S: kf = acc (bias pre-added); ar in SMEM (ars4).
#define EPI_RK4(S)                                                             \
    do {                                                                       \
        _Pragma("unroll")                                                      \
        for (int m = 0; m < 2; m++) {                                          \
            float stm[4][4];                                                   \
            _Pragma("unroll")                                                  \
            for (int t = 0; t < 4; t++) {                                      \
                int q = m * 4 + t;                                             \
                float4 a4;                                                     \
                if (S != 0) a4 = ars4[q * 256 + tid];                          \
                if (S == 0) {                                                  \
                    a4.x = fmaf(h6, acc[m][t][0], zr[m][t][0]);                \
                    a4.y = fmaf(h6, acc[m][t][1], zr[m][t][1]);                \
                    a4.z = fmaf(h6, acc[m][t][2], zr[m][t][2]);                \
                    a4.w = fmaf(h6, acc[m][t][3], zr[m][t][3]);                \
                    stm[t][0] = fmaf(h2, acc[m][t][0], zr[m][t][0]);           \
                    stm[t][1] = fmaf(h2, acc[m][t][1], zr[m][t][1]);           \
                    stm[t][2] = fmaf(h2, acc[m][t][2], zr[m][t][2]);           \
                    stm[t][3] = fmaf(h2, acc[m][t][3], zr[m][t][3]);           \
                    ars4[q * 256 + tid] = a4;                                  \
                } else if (S == 1) {                                           \
                    a4.x = fmaf(h3, acc[m][t][0], a4.x);                       \
                    a4.y = fmaf(h3, acc[m][t][1], a4.y);                       \
                    a4.z = fmaf(h3, acc[m][t][2], a4.z);                       \
                    a4.w = fmaf(h3, acc[m][t][3], a4.w);                       \
                    stm[t][0] = fmaf(h2, acc[m][t][0], zr[m][t][0]);           \
                    stm[t][1] = fmaf(h2, acc[m][t][1], zr[m][t][1]);           \
                    stm[t][2] = fmaf(h2, acc[m][t][2], zr[m][t][2]);           \
                    stm[t][3] = fmaf(h2, acc[m][t][3], zr[m][t][3]);           \
                    ars4[q * 256 + tid] = a4;                                  \
                } else if (S == 2) {                                           \
                    a4.x = fmaf(h3, acc[m][t][0], a4.x);                       \
                    a4.y = fmaf(h3, acc[m][t][1], a4.y);                       \
                    a4.z = fmaf(h3, acc[m][t][2], a4.z);                       \
                    a4.w = fmaf(h3, acc[m][t][3], a4.w);                       \
                    stm[t][0] = fmaf(hs, acc[m][t][0], zr[m][t][0]);           \
                    stm[t][1] = fmaf(hs, acc[m][t][1], zr[m][t][1]);           \
                    stm[t][2] = fmaf(hs, acc[m][t][2], zr[m][t][2]);           \
                    stm[t][3] = fmaf(hs, acc[m][t][3], zr[m][t][3]);           \
                    ars4[q * 256 + tid] = a4;                                  \
                } else {                                                       \
                    zr[m][t][0] = fmaf(h6, acc[m][t][0], a4.x);                \
                    zr[m][t][1] = fmaf(h6, acc[m][t][1], a4.y);                \
                    zr[m][t][2] = fmaf(h6, acc[m][t][2], a4.z);                \
                    zr[m][t][3] = fmaf(h6, acc[m][t][3], a4.w);                \
                    stm[t][0] = zr[m][t][0]; stm[t][1] = zr[m][t][1];          \
                    stm[t][2] = zr[m][t][2]; stm[t][3] = zr[m][t][3];          \
                }                                                              \
            }                                                                  \
            uint4 q0, q1;                                                      \
            q0.x = pack2(stm[0][0], stm[0][1]); q0.y = pack2(stm[0][2], stm[0][3]); \
            q0.z = pack2(stm[1][0], stm[1][1]); q0.w = pack2(stm[1][2], stm[1][3]); \
            q1.x = pack2(stm[2][0], stm[2][1]); q1.y = pack2(stm[2][2], stm[2][3]); \
            q1.z = pack2(stm[3][0], stm[3][1]); q1.w = pack2(stm[3][2], stm[3][3]); \
            Af[m * 512 + sidx0] = q0;                                          \
            Af[m * 512 + sidx1] = q1;                                          \
        }                                                                      \
    } while (0)

#define RK4_STAGE(S)                                                           \
    do {                                                                       \
        gemm_w1(Af, w1p, bw, lane, nt0, aidx, bias1, acc);                     \
        PRELOAD_WIN();                                                         \
        EPI_TANH();                                                            \
        __syncthreads();                                                       \
        gemm_w2(Hf, W2g, win, lane, nt0, aidx, bias2, acc);                    \
        PRELOAD_BW();                                                          \
        EPI_RK4(S);                                                            \
        __syncthreads();                                                       \
    } while (0)

    for (int s = 0; s < TLEN - 1; s++) {
        const float hs = tg[s + 1] - tg[s];
        const float h6 = hs * (1.0f / 6.0f);
        const float h3 = hs * (1.0f / 3.0f);
        const float h2 = hs * 0.5f;
        RK4_STAGE(0);
        RK4_STAGE(1);
        RK4_STAGE(2);
        RK4_STAGE(3);
    }

#pragma unroll
    for (int m = 0; m < 2; m++)
#pragma unroll
        for (int t = 0; t < 4; t++) {
            int cb = (nt0 + t) * 8 + 2 * c0;
            int rbase = row0 + m * 16;
            float2 v0 = {zr[m][t][0], zr[m][t][1]};
            float2 v1 = {zr[m][t][2], zr[m][t][3]};
            *reinterpret_cast<float2*>(&out[(rbase + r0) * ZDIM + cb])     = v0;
            *reinterpret_cast<float2*>(&out[(rbase + r0 + 8) * ZDIM + cb]) = v1;
        }
}

extern "C" void kernel_launch(void* const* d_in, const int* in_sizes, int n_in,
                              void* d_out, int out_size)
{
    const float* z0 = (const float*)d_in[0];
    const float* t  = (const float*)d_in[1];
    const float* W1 = (const float*)d_in[2];
    const float* b1 = (const float*)d_in[3];
    const float* W2 = (const float*)d_in[4];
    const float* b2 = (const float*)d_in[5];
    float* out = (float*)d_out;

    cudaFuncSetAttribute(node_kernel,
                         cudaFuncAttributeMaxDynamicSharedMemorySize, SMEM_TOT);

    prep_kernel<<<64, 256>>>(W1, W2);
    node_kernel<<<NCTA, 256, SMEM_TOT>>>(z0, t, b1, b2, out);
}

// round 11
// speedup vs baseline: 2.0133x; 1.7081x over previous
#include <cuda_runtime.h>
#include <cuda_fp16.h>
#include <stdint.h>

// NeuralODE RK4, fp16 mma (m16n8k16, fp32 accum), sm_103a.
// R11 = R5 (best: 833us) + register-neutral epilogue surgery:
//   1) tanh.approx.f16x2 (pack first, 8 MUFU/thread instead of 16)
//   2) STS-first RK4 epilogue (ar updates moved off pre-barrier path)
//   3) pre-barrier W1 kt=0 fragment preload (latency hides under barrier)
// 64 CTAs x 256 threads; W1 in SMEM, W2 persistent in registers.

#define ZDIM 256
#define TLEN 128
#define MROW 16
#define NCTA 64
#define NKT  16           // K/16
#define NNT  32           // N/8
#define ASP  132          // A smem row stride in half2 words (conflict-free)
#define WREC (NKT * NNT * 32)          // uint2 records per matrix (128KB)

#define SMEM_W1   0
#define SMEM_ATF  (WREC * 8)                       // 131072
#define SMEM_HTF  (SMEM_ATF + MROW * ASP * 4)
#define SMEM_TOT  (SMEM_HTF + MROW * ASP * 4)      // ~144.5 KB

__device__ uint2 WfG[2 * WREC];   // fragment-layout fp16 weights (prep output)

// ---- prep: W[k][n] row-major fp32 -> fp16 B-fragment layout ----
__global__ void prep_kernel(const float* __restrict__ W1, const float* __restrict__ W2)
{
    int idx = blockIdx.x * blockDim.x + threadIdx.x;
    if (idx >= 2 * WREC) return;
    int lane = idx & 31;
    int nt   = (idx >> 5) & 31;
    int kt   = (idx >> 10) & 15;
    int g    = idx >> 14;
    const float* W = g ? W2 : W1;
    int k0 = kt * 16 + 2 * (lane & 3);
    int n  = nt * 8 + (lane >> 2);
    __half2 lo = __floats2half2_rn(W[k0 * ZDIM + n],       W[(k0 + 1) * ZDIM + n]);
    __half2 hi = __floats2half2_rn(W[(k0 + 8) * ZDIM + n], W[(k0 + 9) * ZDIM + n]);
    uint2 v;
    v.x = *reinterpret_cast<unsigned*>(&lo);
    v.y = *reinterpret_cast<unsigned*>(&hi);
    WfG[idx] = v;
}

#define MMA16(ACC, A0, A1, A2, A3, B) \
    asm volatile("mma.sync.aligned.m16n8k16.row.col.f32.f16.f16.f32 " \
                 "{%0,%1,%2,%3}, {%4,%5,%6,%7}, {%8,%9}, {%0,%1,%2,%3};" \
                 : "+f"(ACC[0]), "+f"(ACC[1]), "+f"(ACC[2]), "+f"(ACC[3]) \
                 : "r"(A0), "r"(A1), "r"(A2), "r"(A3), "r"(B.x), "r"(B.y))

__device__ __forceinline__ unsigned pack2(float a, float b) {
    __half2 h = __floats2half2_rn(a, b);
    return *reinterpret_cast<unsigned*>(&h);
}
__device__ __forceinline__ unsigned tanh_h2(unsigned x) {
    unsigned y;
    asm("tanh.approx.f16x2 %0, %1;" : "=r"(y) : "r"(x));
    return y;
}

// GEMM1: A from SMEM (scalar frag layout), B (W1) from SMEM; kt=0 B frags
// arrive preloaded in b[4] (loaded before the preceding barrier).
__device__ __forceinline__ void gemm_w1(const unsigned* __restrict__ As,
                                        const uint2* __restrict__ w1s,
                                        uint2 b[4],
                                        int lane, int nt0,
                                        const float bias[4][2], float acc[4][4])
{
    const int r0 = lane >> 2;
    const int c0 = lane & 3;
#pragma unroll
    for (int t = 0; t < 4; t++) {
        acc[t][0] = bias[t][0]; acc[t][1] = bias[t][1];
        acc[t][2] = bias[t][0]; acc[t][3] = bias[t][1];
    }

    unsigned a0 = As[r0 * ASP + c0];
    unsigned a1 = As[(r0 + 8) * ASP + c0];
    unsigned a2 = As[r0 * ASP + c0 + 4];
    unsigned a3 = As[(r0 + 8) * ASP + c0 + 4];

#pragma unroll
    for (int kt = 0; kt < NKT; kt++) {
        unsigned n0, n1, n2, n3;
        uint2 bn[4];
        if (kt + 1 < NKT) {
            const unsigned* An = As + (kt + 1) * 8;
            n0 = An[r0 * ASP + c0];
            n1 = An[(r0 + 8) * ASP + c0];
            n2 = An[r0 * ASP + c0 + 4];
            n3 = An[(r0 + 8) * ASP + c0 + 4];
#pragma unroll
            for (int t = 0; t < 4; t++)
                bn[t] = w1s[((kt + 1) * NNT + nt0 + t) * 32 + lane];
        }
        MMA16(acc[0], a0, a1, a2, a3, b[0]);
        MMA16(acc[1], a0, a1, a2, a3, b[1]);
        MMA16(acc[2], a0, a1, a2, a3, b[2]);
        MMA16(acc[3], a0, a1, a2, a3, b[3]);
        a0 = n0; a1 = n1; a2 = n2; a3 = n3;
#pragma unroll
        for (int t = 0; t < 4; t++) b[t] = bn[t];
    }
}

// GEMM2: A from SMEM, B (W2) from persistent registers — zero B loads.
__device__ __forceinline__ void gemm_w2(const unsigned* __restrict__ As,
                                        const uint2 w2r[NKT][4],
                                        int lane,
                                        const float bias[4][2], float acc[4][4])
{
    const int r0 = lane >> 2;
    const int c0 = lane & 3;
#pragma unroll
    for (int t = 0; t < 4; t++) {
        acc[t][0] = bias[t][0]; acc[t][1] = bias[t][1];
        acc[t][2] = bias[t][0]; acc[t][3] = bias[t][1];
    }

    unsigned a0 = As[r0 * ASP + c0];
    unsigned a1 = As[(r0 + 8) * ASP + c0];
    unsigned a2 = As[r0 * ASP + c0 + 4];
    unsigned a3 = As[(r0 + 8) * ASP + c0 + 4];

#pragma unroll
    for (int kt = 0; kt < NKT; kt++) {
        unsigned n0, n1, n2, n3;
        if (kt + 1 < NKT) {
            const unsigned* An = As + (kt + 1) * 8;
            n0 = An[r0 * ASP + c0];
            n1 = An[(r0 + 8) * ASP + c0];
            n2 = An[r0 * ASP + c0 + 4];
            n3 = An[(r0 + 8) * ASP + c0 + 4];
        }
        MMA16(acc[0], a0, a1, a2, a3, w2r[kt][0]);
        MMA16(acc[1], a0, a1, a2, a3, w2r[kt][1]);
        MMA16(acc[2], a0, a1, a2, a3, w2r[kt][2]);
        MMA16(acc[3], a0, a1, a2, a3, w2r[kt][3]);
        a0 = n0; a1 = n1; a2 = n2; a3 = n3;
    }
}

__global__ void __launch_bounds__(256, 1)
node_kernel(const float* __restrict__ z0, const float* __restrict__ tg,
            const float* __restrict__ b1, const float* __restrict__ b2,
            float* __restrict__ out)
{
    extern __shared__ unsigned char smem_raw[];
    uint2*    w1s = reinterpret_cast<uint2*>(smem_raw + SMEM_W1);
    unsigned* Atf = reinterpret_cast<unsigned*>(smem_raw + SMEM_ATF);
    unsigned* Htf = reinterpret_cast<unsigned*>(smem_raw + SMEM_HTF);

    const int tid  = threadIdx.x;
    const int lane = tid & 31;
    const int wid  = tid >> 5;           // 0..7
    const int nt0  = wid * 4;            // 4 n-tiles per warp
    const int r0   = lane >> 2;
    const int c0   = lane & 3;
    const int row0 = blockIdx.x * MROW;

    // ---- W1 fragments -> SMEM (once) ----
    {
        const uint4* src = reinterpret_cast<const uint4*>(WfG);
        uint4* dst = reinterpret_cast<uint4*>(w1s);
#pragma unroll
        for (int i = 0; i < WREC / 2 / 256; i++)
            dst[i * 256 + tid] = src[i * 256 + tid];
    }

    // ---- W2 fragments -> persistent registers (once, 128 regs) ----
    uint2 w2r[NKT][4];
    {
        const uint2* w2g = WfG + WREC;
#pragma unroll
        for (int kt = 0; kt < NKT; kt++)
#pragma unroll
            for (int t = 0; t < 4; t++)
                w2r[kt][t] = w2g[(kt * NNT + nt0 + t) * 32 + lane];
    }

    float bias1[4][2], bias2[4][2];
#pragma unroll
    for (int t = 0; t < 4; t++) {
        int cb = (nt0 + t) * 8 + 2 * c0;
        bias1[t][0] = b1[cb]; bias1[t][1] = b1[cb + 1];
        bias2[t][0] = b2[cb]; bias2[t][1] = b2[cb + 1];
    }

    float zr[4][4], ar[4][4], acc[4][4];
    uint2 bw[4];

#define PRELOAD_BW()                                                           \
    do {                                                                       \
        _Pragma("unroll")                                                      \
        for (int t = 0; t < 4; t++) bw[t] = w1s[(nt0 + t) * 32 + lane];        \
    } while (0)

    // ---- initial state ----
#pragma unroll
    for (int t = 0; t < 4; t++) {
        int cb = (nt0 + t) * 8 + 2 * c0;
        float2 v0 = *reinterpret_cast<const float2*>(&z0[(row0 + r0) * ZDIM + cb]);
        float2 v1 = *reinterpret_cast<const float2*>(&z0[(row0 + r0 + 8) * ZDIM + cb]);
        zr[t][0] = v0.x; zr[t][1] = v0.y; zr[t][2] = v1.x; zr[t][3] = v1.y;
        int cu = (nt0 + t) * 4 + c0;
        Atf[r0 * ASP + cu]       = pack2(v0.x, v0.y);
        Atf[(r0 + 8) * ASP + cu] = pack2(v1.x, v1.y);
    }
    PRELOAD_BW();
    __syncthreads();

    // f(z): GEMM1 -> pack -> tanh.f16x2 -> STS -> sync -> GEMM2
#define FEVAL()                                                                \
    do {                                                                       \
        gemm_w1(Atf, w1s, bw, lane, nt0, bias1, acc);                          \
        _Pragma("unroll")                                                      \
        for (int t = 0; t < 4; t++) {                                          \
            int cu = (nt0 + t) * 4 + c0;                                       \
            Htf[r0 * ASP + cu]       = tanh_h2(pack2(acc[t][0], acc[t][1]));   \
            Htf[(r0 + 8) * ASP + cu] = tanh_h2(pack2(acc[t][2], acc[t][3]));   \
        }                                                                      \
        __syncthreads();                                                       \
        gemm_w2(Htf, w2r, lane, bias2, acc);                                   \
    } while (0)

    // Stage epilogue: STS of staged z FIRST (pre-barrier critical path),
    // ar/zr register updates after.
    for (int s = 0; s < TLEN - 1; s++) {
        const float hs = tg[s + 1] - tg[s];
        const float h6 = hs * (1.0f / 6.0f);
        const float h3 = hs * (1.0f / 3.0f);
        const float h2 = hs * 0.5f;

        // ---- k1 ----
        FEVAL();
#pragma unroll
        for (int t = 0; t < 4; t++) {
            int cu = (nt0 + t) * 4 + c0;
            Atf[r0 * ASP + cu] =
                pack2(fmaf(h2, acc[t][0], zr[t][0]), fmaf(h2, acc[t][1], zr[t][1]));
            Atf[(r0 + 8) * ASP + cu] =
                pack2(fmaf(h2, acc[t][2], zr[t][2]), fmaf(h2, acc[t][3], zr[t][3]));
        }
#pragma unroll
        for (int t = 0; t < 4; t++)
#pragma unroll
            for (int d = 0; d < 4; d++)
                ar[t][d] = fmaf(h6, acc[t][d], zr[t][d]);
        PRELOAD_BW();
        __syncthreads();

        // ---- k2 ----
        FEVAL();
#pragma unroll
        for (int t = 0; t < 4; t++) {
            int cu = (nt0 + t) * 4 + c0;
            Atf[r0 * ASP + cu] =
                pack2(fmaf(h2, acc[t][0], zr[t][0]), fmaf(h2, acc[t][1], zr[t][1]));
            Atf[(r0 + 8) * ASP + cu] =
                pack2(fmaf(h2, acc[t][2], zr[t][2]), fmaf(h2, acc[t][3], zr[t][3]));
        }
#pragma unroll
        for (int t = 0; t < 4; t++)
#pragma unroll
            for (int d = 0; d < 4; d++)
                ar[t][d] = fmaf(h3, acc[t][d], ar[t][d]);
        PRELOAD_BW();
        __syncthreads();

        // ---- k3 ----
        FEVAL();
#pragma unroll
        for (int t = 0; t < 4; t++) {
            int cu = (nt0 + t) * 4 + c0;
            Atf[r0 * ASP + cu] =
                pack2(fmaf(hs, acc[t][0], zr[t][0]), fmaf(hs, acc[t][1], zr[t][1]));
            Atf[(r0 + 8) * ASP + cu] =
                pack2(fmaf(hs, acc[t][2], zr[t][2]), fmaf(hs, acc[t][3], zr[t][3]));
        }
#pragma unroll
        for (int t = 0; t < 4; t++)
#pragma unroll
            for (int d = 0; d < 4; d++)
                ar[t][d] = fmaf(h3, acc[t][d], ar[t][d]);
        PRELOAD_BW();
        __syncthreads();

        // ---- k4 + state update ----
        FEVAL();
#pragma unroll
        for (int t = 0; t < 4; t++) {
#pragma unroll
            for (int d = 0; d < 4; d++)
                zr[t][d] = fmaf(h6, acc[t][d], ar[t][d]);
            int cu = (nt0 + t) * 4 + c0;
            Atf[r0 * ASP + cu]       = pack2(zr[t][0], zr[t][1]);
            Atf[(r0 + 8) * ASP + cu] = pack2(zr[t][2], zr[t][3]);
        }
        PRELOAD_BW();
        __syncthreads();
    }

#pragma unroll
    for (int t = 0; t < 4; t++) {
        int cb = (nt0 + t) * 8 + 2 * c0;
        float2 v0 = {zr[t][0], zr[t][1]};
        float2 v1 = {zr[t][2], zr[t][3]};
        *reinterpret_cast<float2*>(&out[(row0 + r0) * ZDIM + cb])     = v0;
        *reinterpret_cast<float2*>(&out[(row0 + r0 + 8) * ZDIM + cb]) = v1;
    }
}

extern "C" void kernel_launch(void* const* d_in, const int* in_sizes, int n_in,
                              void* d_out, int out_size)
{
    const float* z0 = (const float*)d_in[0];
    const float* t  = (const float*)d_in[1];
    const float* W1 = (const float*)d_in[2];
    const float* b1 = (const float*)d_in[3];
    const float* W2 = (const float*)d_in[4];
    const float* b2 = (const float*)d_in[5];
    float* out = (float*)d_out;

    cudaFuncSetAttribute(node_kernel,
                         cudaFuncAttributeMaxDynamicSharedMemorySize, SMEM_TOT);

    prep_kernel<<<(2 * WREC + 255) / 256, 256>>>(W1, W2);
    node_kernel<<<NCTA, 256, SMEM_TOT>>>(z0, t, b1, b2, out);
}